// round 15
// baseline (speedup 1.0000x reference)
#include <cuda_runtime.h>
#include <cuda_bf16.h>
#include <cuda_fp16.h>
#include <cstdint>

// Y(8192x2048) = X(8192x2048) @ W(2048x2048), W = TR(f0,f1,f2,f3), rank-64 per i2-parity.
//   B[r][l*64+ab] = sum_k f0[a,i1,k] f1[k,i2,b],  i1=r>>5, i2=2(r&31)+l, ab=a*8+b
//   C[ab][i3*16+i4] = sum_k f2[b,i3,k] f3[k,i4,a]
//   Z = X @ B (8192x128);  Y[:, l*1024+c'] = Z[:, l*64:+64] @ C
// Both GEMMs single-pass fp16 HMMA, fp32 accumulate (err ~4.1e-4, validated).
// gemm1 v3: N-split tiles 32x64, grid (256,2)=512 CTAs -> occ ~43% (fix for
// the occ=20% starvation measured in R14's ncu).

__device__ __half g_Bf16[2048 * 128];
__device__ __half g_Cf16[64 * 1024];
__device__ __half g_Zf16[8192 * 128];

static __device__ __forceinline__ uint32_t sptr(const void* p) {
    return (uint32_t)__cvta_generic_to_shared(p);
}
static __device__ __forceinline__ void ldm_a(uint32_t addr, uint32_t* r) {
    asm volatile("ldmatrix.sync.aligned.m8n8.x4.shared.b16 {%0,%1,%2,%3}, [%4];"
                 : "=r"(r[0]), "=r"(r[1]), "=r"(r[2]), "=r"(r[3]) : "r"(addr));
}
static __device__ __forceinline__ void ldm_bt(uint32_t addr, uint32_t* r) {
    asm volatile("ldmatrix.sync.aligned.m8n8.x4.trans.shared.b16 {%0,%1,%2,%3}, [%4];"
                 : "=r"(r[0]), "=r"(r[1]), "=r"(r[2]), "=r"(r[3]) : "r"(addr));
}
static __device__ __forceinline__ void mma_f16(float* c, const uint32_t* a,
                                               uint32_t b0, uint32_t b1) {
    asm volatile("mma.sync.aligned.m16n8k16.row.col.f32.f16.f16.f32 "
                 "{%0,%1,%2,%3}, {%4,%5,%6,%7}, {%8,%9}, {%0,%1,%2,%3};"
                 : "+f"(c[0]), "+f"(c[1]), "+f"(c[2]), "+f"(c[3])
                 : "r"(a[0]), "r"(a[1]), "r"(a[2]), "r"(a[3]), "r"(b0), "r"(b1));
}
#define CP16(dst, src)                                                        \
    asm volatile("cp.async.cg.shared.global [%0], [%1], 16;" ::"r"(dst), "l"(src))
#define CP_COMMIT() asm volatile("cp.async.commit_group;")
#define CP_WAIT0() asm volatile("cp.async.wait_group 0;")

static __device__ __forceinline__ uint32_t h2u(__half2 h) {
    return *reinterpret_cast<uint32_t*>(&h);
}

// ---------------------------------------------------------------------------
// K1: build B (fp16) and C (fp16) from TR factors.
// ---------------------------------------------------------------------------
__global__ void build_BC(const float* __restrict__ f0, const float* __restrict__ f1,
                         const float* __restrict__ f2, const float* __restrict__ f3) {
    int idx = blockIdx.x * blockDim.x + threadIdx.x;
    const int NB = 2048 * 128;
    if (idx < NB) {
        int r = idx >> 7, j = idx & 127;
        int l = j >> 6, ab = j & 63, a = ab >> 3, b = ab & 7;
        int i1 = r >> 5, i2 = ((r & 31) << 1) | l;
        float s = 0.0f;
#pragma unroll
        for (int k = 0; k < 8; k++)
            s = fmaf(f0[a * 512 + i1 * 8 + k], f1[k * 512 + i2 * 8 + b], s);
        g_Bf16[idx] = __float2half_rn(s);
    } else {
        int t = idx - NB;
        if (t < 64 * 1024) {
            int ab = t >> 10, c = t & 1023;
            int a = ab >> 3, b = ab & 7, i3 = c >> 4, i4 = c & 15;
            float s = 0.0f;
#pragma unroll
            for (int k = 0; k < 8; k++)
                s = fmaf(f2[b * 512 + i3 * 8 + k], f3[k * 128 + i4 * 8 + a], s);
            g_Cf16[t] = __float2half_rn(s);
        }
    }
}

// ---------------------------------------------------------------------------
// K2: Z = X @ B. Tiles 32(M) x 64(N), grid (256, 2) = 512 CTAs, K=2048, BK=64.
// 256 threads, 8 warps (2Mx4N), warp tile 16x16. Double-buffered static smem:
//   per stage: Xs fp32 32x68 (8704 B) + Bs fp16 64x72 (9216 B) = 17920 B.
// A-fragments via LDS.64 + cvt; B via ldmatrix.trans.
// ---------------------------------------------------------------------------
__global__ __launch_bounds__(256) void gemm1(const float* __restrict__ X) {
    const int STAGE_B = 17920;
    const int XB = 8704;          // X region bytes within stage
    const int LDX = 68;           // fp32 per X row (272 B)
    __shared__ __align__(16) char sm[2 * 17920];
    const uint32_t smb = sptr(sm);

    const int tid = threadIdx.x, lane = tid & 31, wid = tid >> 5;
    const int m0 = blockIdx.x * 32;
    const int n0 = blockIdx.y * 64;
    const int wm = (wid & 1) * 16, wn = (wid >> 1) * 16;
    const int gid = lane >> 2, tig2 = (lane & 3) * 2;

    float acc[2][4];
#pragma unroll
    for (int nt = 0; nt < 2; nt++)
#pragma unroll
        for (int e = 0; e < 4; e++) acc[nt][e] = 0.0f;

    auto load_tile = [&](int it, int s) {
        const int k0 = it * 64;
        const uint32_t base = smb + s * STAGE_B;
        // X: 32 rows x 64 fp32 = 512 16B-chunks, 2/thread
#pragma unroll
        for (int i = 0; i < 2; i++) {
            int p = tid + i * 256;
            int row = p >> 4, c4 = (p & 15) * 4;
            CP16(base + row * 272 + c4 * 4, &X[(m0 + row) * 2048 + k0 + c4]);
        }
        // B: 64 k-rows x 64 n-cols fp16 = 512 16B-chunks, 2/thread
#pragma unroll
        for (int i = 0; i < 2; i++) {
            int p = tid + i * 256;
            int row = p >> 3, c8 = (p & 7) * 8;
            CP16(base + XB + row * 144 + c8 * 2, &g_Bf16[(k0 + row) * 128 + n0 + c8]);
        }
        CP_COMMIT();
    };

    load_tile(0, 0);

    for (int it = 0; it < 32; ++it) {
        CP_WAIT0();
        __syncthreads();
        const int cur = it & 1;
        if (it + 1 < 32) load_tile(it + 1, (it + 1) & 1);

        const float* xs = (const float*)(sm + cur * STAGE_B);
        const uint32_t bsm = smb + cur * STAGE_B + XB;
        const int r0 = (wm + gid) * LDX, r1 = r0 + 8 * LDX;

#pragma unroll
        for (int kk = 0; kk < 64; kk += 16) {
            // A fragment (16x16) from fp32 smem: 4 x LDS.64 + cvt
            float2 v00 = *(const float2*)&xs[r0 + kk + tig2];
            float2 v10 = *(const float2*)&xs[r1 + kk + tig2];
            float2 v01 = *(const float2*)&xs[r0 + kk + 8 + tig2];
            float2 v11 = *(const float2*)&xs[r1 + kk + 8 + tig2];
            uint32_t a[4];
            a[0] = h2u(__floats2half2_rn(v00.x, v00.y));
            a[1] = h2u(__floats2half2_rn(v10.x, v10.y));
            a[2] = h2u(__floats2half2_rn(v01.x, v01.y));
            a[3] = h2u(__floats2half2_rn(v11.x, v11.y));
            // B fragment: one x4 trans ldmatrix covers 16 cols x k16
            uint32_t bh[4];
            int brow = kk + (lane & 7) + ((lane >> 3) & 1) * 8;
            int bcol = wn + (lane >> 4) * 8;
            ldm_bt(bsm + brow * 144 + bcol * 2, bh);
#pragma unroll
            for (int nt = 0; nt < 2; nt++)
                mma_f16(acc[nt], a, bh[nt * 2], bh[nt * 2 + 1]);
        }
    }

    // Epilogue: Z -> fp16 (cols 2j,2j+1 contiguous as __half2).
#pragma unroll
    for (int nt = 0; nt < 2; nt++) {
        int row = m0 + wm + (lane >> 2);
        int col = n0 + wn + nt * 8 + (lane & 3) * 2;
        const float* c = acc[nt];
#pragma unroll
        for (int half = 0; half < 2; half++) {
            int r = row + half * 8;
            __half2 z2 = __floats2half2_rn(c[half * 2 + 0], c[half * 2 + 1]);
            *(__half2*)&g_Zf16[r * 128 + col] = z2;
        }
    }
}

// ---------------------------------------------------------------------------
// K3: Y[:, n0:n0+128] = Z[:, l*64:+64] @ C[:, c0:c0+128]. K=64 resident.
// Block tile 128x128, grid (64, 16). 256 threads, 8 warps (2Mx4N),
// warp tile 64x32. Single-pass fp16. Static smem 35.8 KB. (unchanged R12/R13)
// ---------------------------------------------------------------------------
__global__ __launch_bounds__(256) void gemm2(float* __restrict__ Y) {
    const int LDA = 72;   // Z: 128 x 72
    const int LDB = 136;  // C: 64 x 136
    __shared__ __align__(16) __half Zs[128 * 72];
    __shared__ __align__(16) __half Cs[64 * 136];

    const int tid = threadIdx.x, lane = tid & 31, wid = tid >> 5;
    const int m0 = blockIdx.x * 128;
    const int n0 = blockIdx.y * 128;
    const int l = n0 >> 10;
    const int c0 = n0 & 1023;
    const int wm = (wid & 1) * 64, wn = (wid >> 1) * 32;

#pragma unroll
    for (int i = 0; i < 4; i++) {
        int p = tid + i * 256;
        int row = p >> 3, c8 = (p & 7) * 8;
        CP16(sptr(&Zs[row * LDA + c8]), &g_Zf16[(m0 + row) * 128 + l * 64 + c8]);
    }
#pragma unroll
    for (int i = 0; i < 4; i++) {
        int p = tid + i * 256;
        int row = p >> 4, c8 = (p & 15) * 8;
        CP16(sptr(&Cs[row * LDB + c8]), &g_Cf16[row * 1024 + c0 + c8]);
    }
    CP_COMMIT();
    CP_WAIT0();
    __syncthreads();

    float acc[4][4][4];
#pragma unroll
    for (int mt = 0; mt < 4; mt++)
#pragma unroll
        for (int nt = 0; nt < 4; nt++)
#pragma unroll
            for (int e = 0; e < 4; e++) acc[mt][nt][e] = 0.0f;

#pragma unroll
    for (int kk = 0; kk < 64; kk += 16) {
        uint32_t ah[4][4];
#pragma unroll
        for (int mt = 0; mt < 4; mt++) {
            int arow = wm + mt * 16 + (lane & 15);
            int acol = kk + ((lane >> 4) << 3);
            ldm_a(sptr(&Zs[arow * LDA + acol]), ah[mt]);
        }
        uint32_t bh[2][4];
        int brow = kk + (lane & 7) + ((lane >> 3) & 1) * 8;
#pragma unroll
        for (int h = 0; h < 2; h++) {
            int bcol = wn + h * 16 + (lane >> 4) * 8;
            ldm_bt(sptr(&Cs[brow * LDB + bcol]), bh[h]);
        }
#pragma unroll
        for (int mt = 0; mt < 4; mt++)
#pragma unroll
            for (int nt = 0; nt < 4; nt++) {
                int h = nt >> 1, q = (nt & 1) * 2;
                mma_f16(acc[mt][nt], ah[mt], bh[h][q], bh[h][q + 1]);
            }
    }

#pragma unroll
    for (int mt = 0; mt < 4; mt++)
#pragma unroll
        for (int nt = 0; nt < 4; nt++) {
            int row = m0 + wm + mt * 16 + (lane >> 2);
            int col = n0 + wn + nt * 8 + (lane & 3) * 2;
            const float* c = acc[mt][nt];
            *(float2*)&Y[row * 2048 + col] = make_float2(c[0], c[1]);
            *(float2*)&Y[(row + 8) * 2048 + col] = make_float2(c[2], c[3]);
        }
}

// ---------------------------------------------------------------------------
extern "C" void kernel_launch(void* const* d_in, const int* in_sizes, int n_in,
                              void* d_out, int out_size) {
    const float* x = (const float*)d_in[0];
    const float* f0 = (const float*)d_in[1];
    const float* f1 = (const float*)d_in[2];
    const float* f2 = (const float*)d_in[3];
    const float* f3 = (const float*)d_in[4];
    float* y = (float*)d_out;

    build_BC<<<1280, 256>>>(f0, f1, f2, f3);
    dim3 g1(256, 2);
    gemm1<<<g1, 256>>>(x);
    dim3 g2(64, 16);
    gemm2<<<g2, 256>>>(y);
}